// round 4
// baseline (speedup 1.0000x reference)
#include <cuda_runtime.h>
#include <math.h>

// Problem constants
#define B    32
#define L    2048
#define E    512
#define H    512
#define V    32000
#define D2H  1024          // 2*H, encoder feature dim / GRU input dim
#define SPLITS 32          // L split for reduction: 2048/32 = 64 rows per block

// Output layout (fp32): logp[32000] | h_new[2*32*512=32768] | attn_weights[32*2048=65536]
#define OUT_LOGP  0
#define OUT_HNEW  32000
#define OUT_ATTN  64768
// total 130304

// -------------------- scratch (no allocations allowed) --------------------
__device__ float4 g_partial[B * SPLITS * (D2H / 4)];   // 4 MB
__device__ float  g_cT[D2H * B];                       // c transposed: [k][b]
__device__ float  g_colast[D2H];                       // c_out row 31 = [h_f[31], h_b[31]]
__device__ float  g_logits[V];

// -------------------- K1: partial reduce of encoder_out over L --------------------
// grid (SPLITS, B), block 256. Each thread = one float4 column; 64 rows per block.
__global__ void k1_reduce(const float4* __restrict__ enc)
{
    int s = blockIdx.x;          // 0..31
    int b = blockIdx.y;          // 0..31
    int t = threadIdx.x;         // 0..255 -> float4 column
    int l0 = s * (L / SPLITS);

    float4 acc = make_float4(0.f, 0.f, 0.f, 0.f);
    const float4* base = enc + (size_t)(b * L + l0) * (D2H / 4) + t;
#pragma unroll 8
    for (int l = 0; l < L / SPLITS; ++l) {
        float4 v = base[(size_t)l * (D2H / 4)];
        acc.x += v.x; acc.y += v.y; acc.z += v.z; acc.w += v.w;
    }
    g_partial[(b * SPLITS + s) * (D2H / 4) + t] = acc;
}

// -------------------- K2: finalize c = relu(mean), store transposed --------------------
// grid B, block 256
__global__ void k2_finalize()
{
    int b = blockIdx.x;
    int t = threadIdx.x;
    float4 acc = make_float4(0.f, 0.f, 0.f, 0.f);
#pragma unroll
    for (int s = 0; s < SPLITS; ++s) {
        float4 v = g_partial[(b * SPLITS + s) * (D2H / 4) + t];
        acc.x += v.x; acc.y += v.y; acc.z += v.z; acc.w += v.w;
    }
    const float inv = 1.0f / (float)L;
    float vals[4] = { acc.x * inv, acc.y * inv, acc.z * inv, acc.w * inv };
#pragma unroll
    for (int i = 0; i < 4; ++i) {
        float c = vals[i] > 0.f ? vals[i] : 0.f;
        g_cT[(4 * t + i) * B + b] = c;
    }
}

// -------------------- K3: fused dual GRU cell --------------------
// grid 128 blocks: bit6 = cell, low 6 bits = j-tile (8 gate-indices each).
// block 64 threads: ty = tid>>3 -> j within tile, bx = tid&7 -> 4 batches (bx, bx+8, bx+16, bx+24)
__device__ __forceinline__ float sigmoidf_(float x) { return 1.0f / (1.0f + expf(-x)); }

__global__ void k3_gru(const float* __restrict__ h,
                       const float* __restrict__ Wih_f, const float* __restrict__ Whh_f,
                       const float* __restrict__ bih_f, const float* __restrict__ bhh_f,
                       const float* __restrict__ Wih_b, const float* __restrict__ Whh_b,
                       const float* __restrict__ bih_b, const float* __restrict__ bhh_b,
                       float* __restrict__ out)
{
    int cell = blockIdx.x >> 6;
    int jt   = blockIdx.x & 63;
    const float* Wih = cell ? Wih_b : Wih_f;
    const float* Whh = cell ? Whh_b : Whh_f;
    const float* bih = cell ? bih_b : bih_f;
    const float* bhh = cell ? bhh_b : bhh_f;

    int tid = threadIdx.x;
    int ty  = tid >> 3;     // 0..7
    int bx  = tid & 7;      // 0..7
    int jg  = jt * 8 + ty;  // gate index 0..511

    __shared__ float sW[3][8][64];
    __shared__ float sX[64][33];   // padded transpose tile

    float ai[3][4];
    float ah[3][4];
#pragma unroll
    for (int g = 0; g < 3; ++g)
#pragma unroll
        for (int i = 0; i < 4; ++i) { ai[g][i] = 0.f; ah[g][i] = 0.f; }

    // ---- phase 1: gi = c @ W_ih.T  (K = 1024), c read via g_cT (already transposed) ----
    for (int kt = 0; kt < D2H; kt += 64) {
        for (int idx = tid; idx < 64 * 32; idx += 64) {
            int kk = idx >> 5, b = idx & 31;
            sX[kk][b] = g_cT[(kt + kk) * B + b];
        }
        for (int idx = tid; idx < 3 * 8 * 64; idx += 64) {
            int g = idx / 512, rest = idx % 512;
            int jy = rest >> 6, kk = rest & 63;
            sW[g][jy][kk] = Wih[(g * H + jt * 8 + jy) * D2H + kt + kk];
        }
        __syncthreads();
#pragma unroll 16
        for (int kk = 0; kk < 64; ++kk) {
            float w0 = sW[0][ty][kk], w1 = sW[1][ty][kk], w2 = sW[2][ty][kk];
#pragma unroll
            for (int i = 0; i < 4; ++i) {
                float cv = sX[kk][bx + 8 * i];
                ai[0][i] += w0 * cv;
                ai[1][i] += w1 * cv;
                ai[2][i] += w2 * cv;
            }
        }
        __syncthreads();
    }

    // ---- phase 2: gh = h @ W_hh.T  (K = 512), transpose h tile in smem ----
    const float* hc = h + cell * B * H;
    for (int kt = 0; kt < H; kt += 64) {
        for (int idx = tid; idx < 64 * 32; idx += 64) {
            int b = idx >> 6, kk = idx & 63;
            sX[kk][b] = hc[b * H + kt + kk];
        }
        for (int idx = tid; idx < 3 * 8 * 64; idx += 64) {
            int g = idx / 512, rest = idx % 512;
            int jy = rest >> 6, kk = rest & 63;
            sW[g][jy][kk] = Whh[(g * H + jt * 8 + jy) * H + kt + kk];
        }
        __syncthreads();
#pragma unroll 16
        for (int kk = 0; kk < 64; ++kk) {
            float w0 = sW[0][ty][kk], w1 = sW[1][ty][kk], w2 = sW[2][ty][kk];
#pragma unroll
            for (int i = 0; i < 4; ++i) {
                float hv = sX[kk][bx + 8 * i];
                ah[0][i] += w0 * hv;
                ah[1][i] += w1 * hv;
                ah[2][i] += w2 * hv;
            }
        }
        __syncthreads();
    }

    // ---- combine gates ----
    float bir = bih[jg],        bhr = bhh[jg];
    float biz = bih[H + jg],    bhz = bhh[H + jg];
    float bin = bih[2*H + jg],  bhn = bhh[2*H + jg];
#pragma unroll
    for (int i = 0; i < 4; ++i) {
        int b = bx + 8 * i;
        float hprev = hc[b * H + jg];
        float r = sigmoidf_(ai[0][i] + bir + ah[0][i] + bhr);
        float z = sigmoidf_(ai[1][i] + biz + ah[1][i] + bhz);
        float n = tanhf(ai[2][i] + bin + r * (ah[2][i] + bhn));
        float hn = (1.0f - z) * n + z * hprev;
        out[OUT_HNEW + cell * B * H + b * H + jg] = hn;
        if (b == B - 1) g_colast[cell * H + jg] = hn;
    }
}

// -------------------- K4: vocab GEMV  logits = colast @ out_W.T + out_b --------------------
// grid 4000 blocks x 256 threads; one warp per vocab row (8 rows/block)
__global__ void k4_logits(const float4* __restrict__ outW, const float* __restrict__ outb)
{
    __shared__ float4 sc[D2H / 4];
    int tid = threadIdx.x;
    sc[tid] = ((const float4*)g_colast)[tid];
    __syncthreads();

    int warp = tid >> 5, lane = tid & 31;
    int v = blockIdx.x * 8 + warp;
    const float4* wrow = outW + (size_t)v * (D2H / 4);
    float acc = 0.f;
#pragma unroll
    for (int i = 0; i < 8; ++i) {
        float4 w = wrow[lane + 32 * i];
        float4 c = sc[lane + 32 * i];
        acc += w.x * c.x + w.y * c.y + w.z * c.z + w.w * c.w;
    }
#pragma unroll
    for (int o = 16; o; o >>= 1) acc += __shfl_xor_sync(0xFFFFFFFFu, acc, o);
    if (lane == 0) g_logits[v] = acc + outb[v];
}

// -------------------- K5: log_softmax over 32000 logits, write logp --------------------
// single block, 1024 threads
__global__ void k5_logp(float* __restrict__ out)
{
    const float4* L4 = (const float4*)g_logits;
    int tid = threadIdx.x;
    __shared__ float red[32];
    __shared__ float bval;

    float m = -1e30f;
    for (int i = tid; i < V / 4; i += 1024) {
        float4 v = L4[i];
        m = fmaxf(m, fmaxf(fmaxf(v.x, v.y), fmaxf(v.z, v.w)));
    }
#pragma unroll
    for (int o = 16; o; o >>= 1) m = fmaxf(m, __shfl_xor_sync(0xFFFFFFFFu, m, o));
    if ((tid & 31) == 0) red[tid >> 5] = m;
    __syncthreads();
    if (tid < 32) {
        float t = red[tid];
#pragma unroll
        for (int o = 16; o; o >>= 1) t = fmaxf(t, __shfl_xor_sync(0xFFFFFFFFu, t, o));
        if (tid == 0) bval = t;
    }
    __syncthreads();
    m = bval;
    __syncthreads();

    float s = 0.f;
    for (int i = tid; i < V / 4; i += 1024) {
        float4 v = L4[i];
        s += expf(v.x - m) + expf(v.y - m) + expf(v.z - m) + expf(v.w - m);
    }
#pragma unroll
    for (int o = 16; o; o >>= 1) s += __shfl_xor_sync(0xFFFFFFFFu, s, o);
    if ((tid & 31) == 0) red[tid >> 5] = s;
    __syncthreads();
    if (tid < 32) {
        float t = red[tid];
#pragma unroll
        for (int o = 16; o; o >>= 1) t += __shfl_xor_sync(0xFFFFFFFFu, t, o);
        if (tid == 0) bval = m + logf(t);
    }
    __syncthreads();
    float lse = bval;

    float4* O4 = (float4*)(out + OUT_LOGP);
    for (int i = tid; i < V / 4; i += 1024) {
        float4 v = L4[i];
        v.x -= lse; v.y -= lse; v.z -= lse; v.w -= lse;
        O4[i] = v;
    }
}

// -------------------- K6: attn_weights = 1/L (constant) --------------------
__global__ void k6_attn(float* __restrict__ out)
{
    float4* O4 = (float4*)(out + OUT_ATTN);     // 64768 % 4 == 0
    int idx = blockIdx.x * blockDim.x + threadIdx.x;   // 16384 float4
    const float w = 1.0f / (float)L;
    O4[idx] = make_float4(w, w, w, w);
}

// -------------------- launch --------------------
extern "C" void kernel_launch(void* const* d_in, const int* in_sizes, int n_in,
                              void* d_out, int out_size)
{
    (void)in_sizes; (void)n_in; (void)out_size;
    const float* h_in   = (const float*)d_in[1];
    const float* enc    = (const float*)d_in[2];
    const float* Wih_f  = (const float*)d_in[6];
    const float* Whh_f  = (const float*)d_in[7];
    const float* bih_f  = (const float*)d_in[8];
    const float* bhh_f  = (const float*)d_in[9];
    const float* Wih_b  = (const float*)d_in[10];
    const float* Whh_b  = (const float*)d_in[11];
    const float* bih_b  = (const float*)d_in[12];
    const float* bhh_b  = (const float*)d_in[13];
    const float* outW   = (const float*)d_in[14];
    const float* outb   = (const float*)d_in[15];
    float* out = (float*)d_out;

    // attention output is a constant — independent, launch first
    k6_attn<<<64, 256>>>(out);

    // c = relu(mean_l encoder_out)
    k1_reduce<<<dim3(SPLITS, B), 256>>>((const float4*)enc);
    k2_finalize<<<B, 256>>>();

    // dual GRU -> h_new + colast
    k3_gru<<<128, 64>>>(h_in, Wih_f, Whh_f, bih_f, bhh_f,
                        Wih_b, Whh_b, bih_b, bhh_b, out);

    // vocab GEMV + log_softmax
    k4_logits<<<V / 8, 256>>>((const float4*)outW, outb);
    k5_logp<<<1, 1024>>>(out);
}

// round 6
// speedup vs baseline: 2.3814x; 2.3814x over previous
#include <cuda_runtime.h>
#include <math.h>

// Problem constants
#define B    32
#define L    2048
#define E    512
#define H    512
#define V    32000
#define D2H  1024          // 2*H
#define SPLITS 32          // L split for k1 reduction

// Output layout (fp32): logp[32000] | h_new[32768] | attn_weights[65536]
#define OUT_LOGP  0
#define OUT_HNEW  32000
#define OUT_ATTN  64768

// GRU GEMM geometry: rows = 2 cells * 3 gates * 512 = 3072, K = 1024(ih) + 512(hh)
#define NROWS 3072
#define ROWT  64            // rows per block tile
#define KSPL  3             // k-splits: 0,1 = ih halves (K=512 each), 2 = hh (K=512)

// -------------------- scratch --------------------
__device__ float4 g_partial[B * SPLITS * (D2H / 4)];   // 4 MB
__device__ float  g_cT[D2H * B];                       // c transposed [k][b]
__device__ float  g_gpart[KSPL][NROWS][B];             // GRU gate partials, 1.2 MB
__device__ float  g_colast[D2H];                       // c_out row 31
__device__ float  g_logits[V];

// -------------------- K1: partial reduce of encoder_out over L --------------------
__global__ void k1_reduce(const float4* __restrict__ enc)
{
    int s = blockIdx.x, b = blockIdx.y, t = threadIdx.x;
    int l0 = s * (L / SPLITS);
    float4 acc = make_float4(0.f, 0.f, 0.f, 0.f);
    const float4* base = enc + (size_t)(b * L + l0) * (D2H / 4) + t;
#pragma unroll 8
    for (int l = 0; l < L / SPLITS; ++l) {
        float4 v = base[(size_t)l * (D2H / 4)];
        acc.x += v.x; acc.y += v.y; acc.z += v.z; acc.w += v.w;
    }
    g_partial[(b * SPLITS + s) * (D2H / 4) + t] = acc;
}

// -------------------- K2: finalize c = relu(mean), store transposed --------------------
__global__ void k2_finalize()
{
    int b = blockIdx.x, t = threadIdx.x;
    float4 acc = make_float4(0.f, 0.f, 0.f, 0.f);
#pragma unroll
    for (int s = 0; s < SPLITS; ++s) {
        float4 v = g_partial[(b * SPLITS + s) * (D2H / 4) + t];
        acc.x += v.x; acc.y += v.y; acc.z += v.z; acc.w += v.w;
    }
    const float inv = 1.0f / (float)L;
    float vals[4] = { acc.x * inv, acc.y * inv, acc.z * inv, acc.w * inv };
#pragma unroll
    for (int i = 0; i < 4; ++i) {
        float c = vals[i] > 0.f ? vals[i] : 0.f;
        g_cT[(4 * t + i) * B + b] = c;
    }
}

// -------------------- K3a: split-K register-tiled GEMM for both GRU cells --------------------
// grid = 48 row-tiles * 3 splits = 144 blocks, 128 threads.
// Thread computes 4 batches x 4 rows. k-tile = 32.
__global__ void k3a_gemm(const float* __restrict__ h,
                         const float* __restrict__ Wih_f, const float* __restrict__ Whh_f,
                         const float* __restrict__ Wih_b, const float* __restrict__ Whh_b)
{
    int tile  = blockIdx.x / KSPL;
    int split = blockIdx.x % KSPL;
    int R0    = tile * ROWT;           // global row base (0..3071)
    int cell  = (R0 >= 1536) ? 1 : 0;
    int gr0   = R0 - cell * 1536;      // row within this cell's 1536-row W matrix

    const bool  hh  = (split == 2);
    const float* W  = hh ? (cell ? Whh_b : Whh_f) : (cell ? Wih_b : Wih_f);
    const int    ldw  = hh ? H : D2H;
    const int    koff = hh ? 0 : split * 512;   // column offset into W / g_cT

    __shared__ float sW[32][68];       // [k][row], padded
    __shared__ float sX[32][32];       // [k][batch]

    int tid = threadIdx.x;
    int tx  = tid & 7;                 // batch group: batches 4tx..4tx+3
    int ty  = tid >> 3;                // row group:   rows   4ty..4ty+3

    float acc[4][4];
#pragma unroll
    for (int i = 0; i < 4; ++i)
#pragma unroll
        for (int j = 0; j < 4; ++j) acc[i][j] = 0.f;

    const float4* H4  = (const float4*)(h + (size_t)cell * B * H);
    const float4* cT4 = (const float4*)g_cT;

    for (int kt = 0; kt < 512; kt += 32) {
        // --- load W tile: 64 rows x 32 k, transposed into sW[k][row] ---
#pragma unroll
        for (int i = 0; i < 4; ++i) {
            int idx = tid + i * 128;
            int row = idx >> 3, kg = idx & 7;
            const float4* wr = (const float4*)(W + (size_t)(gr0 + row) * ldw + koff + kt);
            float4 w = wr[kg];
            sW[4 * kg + 0][row] = w.x;
            sW[4 * kg + 1][row] = w.y;
            sW[4 * kg + 2][row] = w.z;
            sW[4 * kg + 3][row] = w.w;
        }
        // --- load X tile into sX[k][b] ---
        if (!hh) {
#pragma unroll
            for (int i = 0; i < 2; ++i) {
                int idx = tid + i * 128;
                int k = idx >> 3, bg = idx & 7;
                ((float4*)&sX[k][0])[bg] = cT4[(size_t)(koff + kt + k) * 8 + bg];
            }
        } else {
#pragma unroll
            for (int i = 0; i < 2; ++i) {
                int idx = tid + i * 128;
                int b = idx >> 3, kg = idx & 7;
                float4 hv = H4[(size_t)b * (H / 4) + (kt >> 2) + kg];
                sX[4 * kg + 0][b] = hv.x;
                sX[4 * kg + 1][b] = hv.y;
                sX[4 * kg + 2][b] = hv.z;
                sX[4 * kg + 3][b] = hv.w;
            }
        }
        __syncthreads();

#pragma unroll
        for (int k = 0; k < 32; ++k) {
            float4 a = ((const float4*)&sX[k][0])[tx];
            float4 w = *(const float4*)&sW[k][4 * ty];
            acc[0][0] += a.x * w.x; acc[0][1] += a.x * w.y; acc[0][2] += a.x * w.z; acc[0][3] += a.x * w.w;
            acc[1][0] += a.y * w.x; acc[1][1] += a.y * w.y; acc[1][2] += a.y * w.z; acc[1][3] += a.y * w.w;
            acc[2][0] += a.z * w.x; acc[2][1] += a.z * w.y; acc[2][2] += a.z * w.z; acc[2][3] += a.z * w.w;
            acc[3][0] += a.w * w.x; acc[3][1] += a.w * w.y; acc[3][2] += a.w * w.z; acc[3][3] += a.w * w.w;
        }
        __syncthreads();
    }

#pragma unroll
    for (int j = 0; j < 4; ++j)
#pragma unroll
        for (int i = 0; i < 4; ++i)
            g_gpart[split][R0 + 4 * ty + j][4 * tx + i] = acc[i][j];
}

// -------------------- K3b: combine partials + gates + nonlinearity --------------------
__device__ __forceinline__ float sigmoidf_(float x) { return 1.0f / (1.0f + expf(-x)); }

__global__ void k3b_gate(const float* __restrict__ h,
                         const float* __restrict__ bih_f, const float* __restrict__ bhh_f,
                         const float* __restrict__ bih_b, const float* __restrict__ bhh_b,
                         float* __restrict__ out)
{
    int idx  = blockIdx.x * 256 + threadIdx.x;
    int b    = idx & 31;
    int j    = (idx >> 5) & 511;
    int cell = idx >> 14;

    const float* bih = cell ? bih_b : bih_f;
    const float* bhh = cell ? bhh_b : bhh_f;
    int Rb = cell * 1536;

    float Gi[3], Gh[3];
#pragma unroll
    for (int g = 0; g < 3; ++g) {
        int R = Rb + g * 512 + j;
        Gi[g] = g_gpart[0][R][b] + g_gpart[1][R][b] + bih[g * 512 + j];
        Gh[g] = g_gpart[2][R][b] + bhh[g * 512 + j];
    }
    float hprev = h[(size_t)cell * B * H + b * H + j];
    float r = sigmoidf_(Gi[0] + Gh[0]);
    float z = sigmoidf_(Gi[1] + Gh[1]);
    float n = tanhf(Gi[2] + r * Gh[2]);
    float hn = (1.0f - z) * n + z * hprev;

    out[OUT_HNEW + cell * B * H + b * H + j] = hn;
    if (b == B - 1) g_colast[cell * H + j] = hn;
}

// -------------------- K4: vocab GEMV --------------------
__global__ void k4_logits(const float4* __restrict__ outW, const float* __restrict__ outb)
{
    __shared__ float4 sc[D2H / 4];
    int tid = threadIdx.x;
    sc[tid] = ((const float4*)g_colast)[tid];
    __syncthreads();

    int warp = tid >> 5, lane = tid & 31;
    int v = blockIdx.x * 8 + warp;
    const float4* wrow = outW + (size_t)v * (D2H / 4);
    float acc = 0.f;
#pragma unroll
    for (int i = 0; i < 8; ++i) {
        float4 w = wrow[lane + 32 * i];
        float4 c = sc[lane + 32 * i];
        acc += w.x * c.x + w.y * c.y + w.z * c.z + w.w * c.w;
    }
#pragma unroll
    for (int o = 16; o; o >>= 1) acc += __shfl_xor_sync(0xFFFFFFFFu, acc, o);
    if (lane == 0) g_logits[v] = acc + outb[v];
}

// -------------------- K5: log_softmax --------------------
__global__ void k5_logp(float* __restrict__ out)
{
    const float4* L4 = (const float4*)g_logits;
    int tid = threadIdx.x;
    __shared__ float red[32];
    __shared__ float bval;

    float m = -1e30f;
    for (int i = tid; i < V / 4; i += 1024) {
        float4 v = L4[i];
        m = fmaxf(m, fmaxf(fmaxf(v.x, v.y), fmaxf(v.z, v.w)));
    }
#pragma unroll
    for (int o = 16; o; o >>= 1) m = fmaxf(m, __shfl_xor_sync(0xFFFFFFFFu, m, o));
    if ((tid & 31) == 0) red[tid >> 5] = m;
    __syncthreads();
    if (tid < 32) {
        float t = red[tid];
#pragma unroll
        for (int o = 16; o; o >>= 1) t = fmaxf(t, __shfl_xor_sync(0xFFFFFFFFu, t, o));
        if (tid == 0) bval = t;
    }
    __syncthreads();
    m = bval;
    __syncthreads();

    float s = 0.f;
    for (int i = tid; i < V / 4; i += 1024) {
        float4 v = L4[i];
        s += expf(v.x - m) + expf(v.y - m) + expf(v.z - m) + expf(v.w - m);
    }
#pragma unroll
    for (int o = 16; o; o >>= 1) s += __shfl_xor_sync(0xFFFFFFFFu, s, o);
    if ((tid & 31) == 0) red[tid >> 5] = s;
    __syncthreads();
    if (tid < 32) {
        float t = red[tid];
#pragma unroll
        for (int o = 16; o; o >>= 1) t += __shfl_xor_sync(0xFFFFFFFFu, t, o);
        if (tid == 0) bval = m + logf(t);
    }
    __syncthreads();
    float lse = bval;

    float4* O4 = (float4*)(out + OUT_LOGP);
    for (int i = tid; i < V / 4; i += 1024) {
        float4 v = L4[i];
        v.x -= lse; v.y -= lse; v.z -= lse; v.w -= lse;
        O4[i] = v;
    }
}

// -------------------- K6: attn_weights = 1/L --------------------
__global__ void k6_attn(float* __restrict__ out)
{
    float4* O4 = (float4*)(out + OUT_ATTN);
    int idx = blockIdx.x * blockDim.x + threadIdx.x;
    const float w = 1.0f / (float)L;
    O4[idx] = make_float4(w, w, w, w);
}

// -------------------- launch --------------------
extern "C" void kernel_launch(void* const* d_in, const int* in_sizes, int n_in,
                              void* d_out, int out_size)
{
    (void)in_sizes; (void)n_in; (void)out_size;
    const float* h_in   = (const float*)d_in[1];
    const float* enc    = (const float*)d_in[2];
    const float* Wih_f  = (const float*)d_in[6];
    const float* Whh_f  = (const float*)d_in[7];
    const float* bih_f  = (const float*)d_in[8];
    const float* bhh_f  = (const float*)d_in[9];
    const float* Wih_b  = (const float*)d_in[10];
    const float* Whh_b  = (const float*)d_in[11];
    const float* bih_b  = (const float*)d_in[12];
    const float* bhh_b  = (const float*)d_in[13];
    const float* outW   = (const float*)d_in[14];
    const float* outb   = (const float*)d_in[15];
    float* out = (float*)d_out;

    k6_attn<<<64, 256>>>(out);

    k1_reduce<<<dim3(SPLITS, B), 256>>>((const float4*)enc);
    k2_finalize<<<B, 256>>>();

    k3a_gemm<<<(NROWS / ROWT) * KSPL, 128>>>(h_in, Wih_f, Whh_f, Wih_b, Whh_b);
    k3b_gate<<<(2 * B * H) / 256, 256>>>(h_in, bih_f, bhh_f, bih_b, bhh_b, out);

    k4_logits<<<V / 8, 256>>>((const float4*)outW, outb);
    k5_logp<<<1, 1024>>>(out);
}